// round 6
// baseline (speedup 1.0000x reference)
#include <cuda_runtime.h>
#include <cuda_fp16.h>
#include <cstdint>

// ============================================================================
// LSTM decoder, B=2048, T=32, H=1024, inference path (pred feedback).
// PERSISTENT kernel: all 32 steps in one launch, W_hh resident in SMEM,
// hand-rolled grid barrier between steps (128 CTAs, 1/SM => all co-resident).
//
// Partition: 64 n-slices (64 gate cols = 16 units) x 2 m-groups (1024 rows).
// Per CTA per step: 4 m-subtiles of 256 rows; GEMM 256x64 x K=1024 fp16
// mma.sync with W read from persistent SMEM; fused LSTM-cell epilogue.
// W columns permuted: col n -> (unit n>>2, gate n&3), gate order i,f,g,o.
// h double-buffered across steps (cross-CTA race fix).
// ============================================================================

#define BATCH 2048
#define TT    32
#define HH    1024
#define N4    4096
#define NCTA  128
#define TNP   64              // gate cols per CTA (16 units)
#define MSUB  256             // rows per subtile
#define NSUB  4               // subtiles per m-group (1024 rows)
#define KCP   64              // K chunk (fp16) = 128 bytes
#define NCHP  (HH / KCP)      // 16
#define PTHREADS 512
#define WSMEM  131072         // 64 rows x 1024 fp16 (16 chunk-tiles x 8KB)
#define ASTAGE 32768          // 256 rows x 128B
#define PSTAGES 3
#define PSMEM (WSMEM + PSTAGES * ASTAGE)   // 229376
#define PSMEM_ALLOC (PSMEM + 1024)
#define GPITCH 68             // gates smem pitch (floats) - conflict-free stores

// Scratch (device globals; no allocation allowed)
__device__ __align__(256) __half g_Wext[(size_t)N4 * HH];        // 8 MB
__device__ __align__(256) __half g_Aext[2][(size_t)BATCH * HH];  // 2 x 4 MB
__device__ __align__(256) float g_c[(size_t)BATCH * HH];         // 8 MB
__device__ __align__(256) float g_predsum[BATCH * TT];
__device__ __align__(256) float g_bias[N4];
__device__ __align__(256) float g_w0[N4];
__device__ __align__(256) float g_w1[N4];
__device__ __align__(256) float g_fcW[HH];
__device__ int g_bar_arrive;
__device__ int g_bar_release;

// ---------------------------------------------------------------------------
// helpers
// ---------------------------------------------------------------------------
__device__ __forceinline__ uint32_t smem_u32(const void* p) {
    uint32_t a;
    asm("{ .reg .u64 t; cvta.to.shared.u64 t, %1; cvt.u32.u64 %0, t; }" : "=r"(a) : "l"(p));
    return a;
}
__device__ __forceinline__ void cp_async16(uint32_t dst, const void* src) {
    asm volatile("cp.async.cg.shared.global [%0], [%1], 16;" :: "r"(dst), "l"(src) : "memory");
}
__device__ __forceinline__ void cp_commit() {
    asm volatile("cp.async.commit_group;" ::: "memory");
}
__device__ __forceinline__ uint32_t sw128(uint32_t off) {
    return off ^ ((off >> 3) & 0x70u);
}
__device__ __forceinline__ void ldsm_x4(uint32_t& r0, uint32_t& r1, uint32_t& r2, uint32_t& r3,
                                        uint32_t addr) {
    asm volatile("ldmatrix.sync.aligned.m8n8.x4.shared.b16 {%0,%1,%2,%3}, [%4];"
                 : "=r"(r0), "=r"(r1), "=r"(r2), "=r"(r3) : "r"(addr));
}
__device__ __forceinline__ void mma_fp16(float* d, const uint32_t* a, const uint32_t* b) {
    asm volatile(
        "mma.sync.aligned.m16n8k16.row.col.f32.f16.f16.f32 "
        "{%0,%1,%2,%3}, {%4,%5,%6,%7}, {%8,%9}, {%0,%1,%2,%3};"
        : "+f"(d[0]), "+f"(d[1]), "+f"(d[2]), "+f"(d[3])
        : "r"(a[0]), "r"(a[1]), "r"(a[2]), "r"(a[3]), "r"(b[0]), "r"(b[1]));
}
__device__ __forceinline__ float sigf(float x) {
    return __fdividef(1.0f, 1.0f + __expf(-x));
}
__device__ __forceinline__ float tanh_f(float x) {
    float xc = fminf(fmaxf(x, -15.0f), 15.0f);
    float e = __expf(2.0f * xc);
    return 1.0f - __fdividef(2.0f, e + 1.0f);
}

// ---------------------------------------------------------------------------
// Prep kernels
// ---------------------------------------------------------------------------
__global__ void prep_weights(const float* __restrict__ W_hh, const float* __restrict__ W_ih,
                             const float* __restrict__ b_ih, const float* __restrict__ b_hh,
                             const float* __restrict__ fc_W) {
    int idx = blockIdx.x * blockDim.x + threadIdx.x;   // 0 .. 4096*1024-1
    int n = idx >> 10, k = idx & 1023;
    int r = (n & 3) * HH + (n >> 2);                   // col n -> orig W_hh row
    g_Wext[(size_t)n * HH + k] = __float2half(W_hh[(size_t)r * HH + k]);
    if (idx < N4) {
        int rr = (idx & 3) * HH + (idx >> 2);
        g_bias[idx] = b_ih[rr] + b_hh[rr];
        g_w0[idx] = W_ih[rr * 2 + 0];
        g_w1[idx] = W_ih[rr * 2 + 1];
    }
    if (idx < HH) g_fcW[idx] = fc_W[idx];
}

__global__ void prep_state(const float* __restrict__ hidden, const float* __restrict__ cell) {
    int idx = blockIdx.x * blockDim.x + threadIdx.x;   // 0 .. 2048*1024-1
    g_c[idx] = cell[idx];
    g_Aext[0][idx] = __float2half(hidden[idx]);
    if (idx < BATCH * TT) g_predsum[idx] = 0.0f;
    if (idx == 0) { g_bar_arrive = 0; g_bar_release = 0; }
}

__global__ void finalize_out(float* __restrict__ out, const float* __restrict__ fc_b) {
    int idx = blockIdx.x * blockDim.x + threadIdx.x;
    if (idx < BATCH * TT) out[idx] = g_predsum[idx] + fc_b[0];
}

// ---------------------------------------------------------------------------
// Persistent kernel
// ---------------------------------------------------------------------------
__global__ void __launch_bounds__(PTHREADS, 1)
persistent_kernel(const float* __restrict__ future_fd, const float* __restrict__ fc_b) {
    extern __shared__ char smem_raw[];
    uint32_t sb = smem_u32(smem_raw);
    uint32_t ab = (sb + 1023u) & ~1023u;
    char* smem = smem_raw + (ab - sb);
    const uint32_t Wbase = ab;
    const uint32_t Abase = ab + WSMEM;

    const int tid = threadIdx.x;
    const int wid = tid >> 5;
    const int lid = tid & 31;
    const int wm = wid & 3;            // 0..3  (64-row block within 256)
    const int wn = wid >> 2;           // 0..3  (16-col block within 64)
    const int n_idx = blockIdx.x >> 1; // 0..63
    const int m_grp = blockIdx.x & 1;  // 0..1
    const int n0 = n_idx * TNP;
    const float fcb = fc_b[0];

    // ---- load persistent W slice: 16 chunk-tiles of 64 rows x 128B ---------
    #pragma unroll 4
    for (int i = tid; i < WSMEM / 16; i += PTHREADS) {
        int chunk = i >> 9;            // 512 x 16B units per chunk-tile
        int within = i & 511;
        int row = within >> 3, q = within & 7;
        uint32_t dst = Wbase + chunk * 8192 + sw128((uint32_t)(row * 128 + q * 16));
        cp_async16(dst, g_Wext + ((size_t)(n0 + row) * HH + chunk * KCP + q * 8));
    }
    cp_commit();
    asm volatile("cp.async.wait_group 0;" ::: "memory");
    __syncthreads();

    // ---- lane constants for ldmatrix addressing ----------------------------
    const int a_lr = lid & 15;
    const int a_ch = (lid >> 4) << 4;
    const int b_nr = (lid & 7) + ((lid >> 4) << 3);
    const int b_ch = ((lid >> 3) & 1) << 4;
    const int g = lid >> 2, tg = lid & 3;

    for (int t = 0; t < TT; t++) {
        const __half* __restrict__ Asrc = g_Aext[t & 1];
        __half* __restrict__ Adst = g_Aext[(t + 1) & 1];

        #pragma unroll 1
        for (int sub = 0; sub < NSUB; sub++) {
            const int mb = m_grp * 1024 + sub * MSUB;

            auto load_a = [&](int c, int s) {
                const uint32_t base = Abase + s * ASTAGE;
                #pragma unroll
                for (int j = 0; j < 4; j++) {
                    int li = tid + j * PTHREADS;
                    int ri = li >> 3, q = li & 7;
                    uint32_t dst = base + sw128((uint32_t)(ri * 128 + q * 16));
                    cp_async16(dst, Asrc + ((size_t)(mb + ri) * HH + c * KCP + q * 8));
                }
                cp_commit();
            };

            float acc[4][2][4];
            #pragma unroll
            for (int i = 0; i < 4; i++)
                #pragma unroll
                for (int j = 0; j < 2; j++)
                    #pragma unroll
                    for (int r = 0; r < 4; r++) acc[i][j][r] = 0.0f;

            load_a(0, 0);
            load_a(1, 1);

            #pragma unroll 1
            for (int c = 0; c < NCHP; c++) {
                if (c < NCHP - 2) asm volatile("cp.async.wait_group 1;" ::: "memory");
                else              asm volatile("cp.async.wait_group 0;" ::: "memory");
                __syncthreads();

                if (c + 2 < NCHP) load_a(c + 2, (c + 2) % PSTAGES);

                const uint32_t As = Abase + (c % PSTAGES) * ASTAGE;
                const uint32_t Ws = Wbase + c * 8192;

                #pragma unroll
                for (int ks = 0; ks < 4; ks++) {
                    uint32_t a[4][4], b[2][2];
                    #pragma unroll
                    for (int mi = 0; mi < 4; mi++) {
                        uint32_t off = (uint32_t)((wm * 64 + mi * 16 + a_lr) * 128 + ks * 32 + a_ch);
                        ldsm_x4(a[mi][0], a[mi][1], a[mi][2], a[mi][3], As + sw128(off));
                    }
                    {
                        uint32_t off = (uint32_t)((wn * 16 + b_nr) * 128 + ks * 32 + b_ch);
                        ldsm_x4(b[0][0], b[0][1], b[1][0], b[1][1], Ws + sw128(off));
                    }
                    #pragma unroll
                    for (int mi = 0; mi < 4; mi++)
                        #pragma unroll
                        for (int j = 0; j < 2; j++)
                            mma_fp16(acc[mi][j], a[mi], b[j]);
                }
            }
            __syncthreads();   // A stages now reusable as gates scratch

            // ---- epilogue for this subtile ---------------------------------
            float* gates = (float*)(smem + WSMEM);   // 256 x GPITCH floats
            {
                const int clb = wn * 16;
                #pragma unroll
                for (int mi = 0; mi < 4; mi++) {
                    const int r = wm * 64 + mi * 16 + g;
                    #pragma unroll
                    for (int j = 0; j < 2; j++) {
                        const int cl = clb + j * 8 + 2 * tg;
                        *(float2*)&gates[r * GPITCH + cl] =
                            make_float2(acc[mi][j][0], acc[mi][j][1]);
                        *(float2*)&gates[(r + 8) * GPITCH + cl] =
                            make_float2(acc[mi][j][2], acc[mi][j][3]);
                    }
                }
            }
            __syncthreads();

            #pragma unroll 2
            for (int it = 0; it < 8; it++) {
                const int idx = tid + it * PTHREADS;   // 4096 = 256 rows x 16 units
                const int row = idx >> 4, u = idx & 15;
                const int n = n0 + 4 * u;
                const int ug = n >> 2;                 // global unit
                const int b = mb + row;

                float4 gv = *(float4*)&gates[row * GPITCH + 4 * u];
                float4 bs = ((const float4*)g_bias)[ug];
                float4 w0 = ((const float4*)g_w0)[ug];
                float4 w1 = ((const float4*)g_w1)[ug];

                float prev = 0.0f;
                if (t > 0) prev = g_predsum[b * TT + (t - 1)] + fcb;
                const float fdv = future_fd[b * TT + t];

                float gi = gv.x + bs.x + prev * w0.x + fdv * w1.x;
                float gf = gv.y + bs.y + prev * w0.y + fdv * w1.y;
                float gg = gv.z + bs.z + prev * w0.z + fdv * w1.z;
                float go = gv.w + bs.w + prev * w0.w + fdv * w1.w;

                float co = g_c[(size_t)b * HH + ug];
                float cn = sigf(gf) * co + sigf(gi) * tanh_f(gg);
                float h  = sigf(go) * tanh_f(cn);
                g_c[(size_t)b * HH + ug] = cn;
                Adst[(size_t)b * HH + ug] = __float2half(h);

                float fcp = h * g_fcW[ug];
                fcp += __shfl_xor_sync(0xFFFFFFFFu, fcp, 1);
                fcp += __shfl_xor_sync(0xFFFFFFFFu, fcp, 2);
                fcp += __shfl_xor_sync(0xFFFFFFFFu, fcp, 4);
                fcp += __shfl_xor_sync(0xFFFFFFFFu, fcp, 8);
                if ((lid & 15) == 0) atomicAdd(&g_predsum[b * TT + t], fcp);
            }
            __syncthreads();   // gates region free before next subtile's loads
        }

        // ---- grid-wide barrier between steps -------------------------------
        if (t < TT - 1) {
            if (tid == 0) {
                __threadfence();
                int a = atomicAdd(&g_bar_arrive, 1);
                if (a == (t + 1) * NCTA - 1) {
                    __threadfence();
                    *(volatile int*)&g_bar_release = t + 1;
                    __threadfence();
                } else {
                    while (*(volatile int*)&g_bar_release < t + 1) __nanosleep(64);
                    __threadfence();
                }
            }
            __syncthreads();
        }
    }
}

// ---------------------------------------------------------------------------
// Host launcher
// ---------------------------------------------------------------------------
extern "C" void kernel_launch(void* const* d_in, const int* in_sizes, int n_in,
                              void* d_out, int out_size) {
    const float* future_fd = (const float*)d_in[0];
    const float* hidden    = (const float*)d_in[1];
    const float* cell      = (const float*)d_in[2];
    const float* W_ih      = (const float*)d_in[3];
    const float* W_hh      = (const float*)d_in[4];
    const float* b_ih      = (const float*)d_in[5];
    const float* b_hh      = (const float*)d_in[6];
    const float* fc_W      = (const float*)d_in[7];
    const float* fc_b      = (const float*)d_in[8];

    cudaFuncSetAttribute(persistent_kernel,
                         cudaFuncAttributeMaxDynamicSharedMemorySize, PSMEM_ALLOC);

    prep_weights<<<(N4 * HH) / 256, 256>>>(W_hh, W_ih, b_ih, b_hh, fc_W);
    prep_state<<<(BATCH * HH) / 256, 256>>>(hidden, cell);
    persistent_kernel<<<NCTA, PTHREADS, PSMEM_ALLOC>>>(future_fd, fc_b);
    finalize_out<<<(BATCH * TT + 255) / 256, 256>>>((float*)d_out, fc_b);
}

// round 7
// speedup vs baseline: 1.2475x; 1.2475x over previous
#include <cuda_runtime.h>
#include <cuda_fp16.h>
#include <cstdint>

// ============================================================================
// LSTM decoder, B=2048, T=32, H=1024, inference path (pred feedback).
// sm_100: fp16 mma.sync GEMM + cp.async 3-stage pipeline, 3 CTAs/SM.
//
// Per step: D[2048,4096] = A[2048,1024](fp16 h) * W[4096,1024]^T (fp16)
// Tile 128x64 (TN=64 so 3 CTAs/SM co-reside: 24 warps/SM hides ldsm->mma RAW
// stalls and per-chunk barriers that capped R5 at tensor=38%).
// W columns permuted: col n -> (unit n>>2, gate n&3), gate order i,f,g,o.
// One kernel launch per time step = grid-wide dependency barrier.
// h double-buffered across steps (cross-CTA race fix).
// ============================================================================

#define BATCH 2048
#define TT    32
#define HH    1024
#define N4    4096
#define KE    1024            // K = H (single fp16 term)
#define TM    128             // M tile
#define TN    64              // N tile
#define KC    64              // K chunk (fp16) = 128 bytes
#define NCH   (KE / KC)       // 16
#define NTHREADS 256
#define STAGES 3
#define STAGE_BYTES 24576     // A 16KB + B 8KB
#define SMEM_BYTES  (1024 + STAGES * STAGE_BYTES)   // 74752
#define GPITCH 68             // gates smem pitch (floats)

// Scratch (device globals; no allocation allowed)
__device__ __align__(256) __half g_Wext[(size_t)N4 * KE];        // 8 MB
__device__ __align__(256) __half g_Aext[2][(size_t)BATCH * KE];  // 2 x 4 MB
__device__ __align__(256) float g_c[(size_t)BATCH * HH];         // 8 MB
__device__ __align__(256) float g_predsum[BATCH * TT];
__device__ __align__(256) float g_bias[N4];
__device__ __align__(256) float g_w0[N4];
__device__ __align__(256) float g_w1[N4];
__device__ __align__(256) float g_fcW[HH];

// ---------------------------------------------------------------------------
// helpers
// ---------------------------------------------------------------------------
__device__ __forceinline__ uint32_t smem_u32(const void* p) {
    uint32_t a;
    asm("{ .reg .u64 t; cvta.to.shared.u64 t, %1; cvt.u32.u64 %0, t; }" : "=r"(a) : "l"(p));
    return a;
}
__device__ __forceinline__ void cp_async16(uint32_t dst, const void* src) {
    asm volatile("cp.async.cg.shared.global [%0], [%1], 16;" :: "r"(dst), "l"(src) : "memory");
}
__device__ __forceinline__ void cp_commit() {
    asm volatile("cp.async.commit_group;" ::: "memory");
}
__device__ __forceinline__ uint32_t sw128(uint32_t off) {
    return off ^ ((off >> 3) & 0x70u);
}
__device__ __forceinline__ void ldsm_x4(uint32_t& r0, uint32_t& r1, uint32_t& r2, uint32_t& r3,
                                        uint32_t addr) {
    asm volatile("ldmatrix.sync.aligned.m8n8.x4.shared.b16 {%0,%1,%2,%3}, [%4];"
                 : "=r"(r0), "=r"(r1), "=r"(r2), "=r"(r3) : "r"(addr));
}
__device__ __forceinline__ void mma_fp16(float* d, const uint32_t* a, const uint32_t* b) {
    asm volatile(
        "mma.sync.aligned.m16n8k16.row.col.f32.f16.f16.f32 "
        "{%0,%1,%2,%3}, {%4,%5,%6,%7}, {%8,%9}, {%0,%1,%2,%3};"
        : "+f"(d[0]), "+f"(d[1]), "+f"(d[2]), "+f"(d[3])
        : "r"(a[0]), "r"(a[1]), "r"(a[2]), "r"(a[3]), "r"(b[0]), "r"(b[1]));
}
__device__ __forceinline__ float sigf(float x) {
    return __fdividef(1.0f, 1.0f + __expf(-x));
}
__device__ __forceinline__ float tanh_f(float x) {
    float xc = fminf(fmaxf(x, -15.0f), 15.0f);
    float e = __expf(2.0f * xc);
    return 1.0f - __fdividef(2.0f, e + 1.0f);
}

// ---------------------------------------------------------------------------
// Prep kernels
// ---------------------------------------------------------------------------
__global__ void prep_weights(const float* __restrict__ W_hh, const float* __restrict__ W_ih,
                             const float* __restrict__ b_ih, const float* __restrict__ b_hh,
                             const float* __restrict__ fc_W) {
    int idx = blockIdx.x * blockDim.x + threadIdx.x;   // 0 .. 4096*1024-1
    int n = idx >> 10, k = idx & 1023;
    int r = (n & 3) * HH + (n >> 2);                   // col n -> orig W_hh row
    g_Wext[(size_t)n * KE + k] = __float2half(W_hh[(size_t)r * HH + k]);
    if (idx < N4) {
        int rr = (idx & 3) * HH + (idx >> 2);
        g_bias[idx] = b_ih[rr] + b_hh[rr];
        g_w0[idx] = W_ih[rr * 2 + 0];
        g_w1[idx] = W_ih[rr * 2 + 1];
    }
    if (idx < HH) g_fcW[idx] = fc_W[idx];
}

__global__ void prep_state(const float* __restrict__ hidden, const float* __restrict__ cell) {
    int idx = blockIdx.x * blockDim.x + threadIdx.x;   // 0 .. 2048*1024-1
    g_c[idx] = cell[idx];
    g_Aext[0][idx] = __float2half(hidden[idx]);
    if (idx < BATCH * TT) g_predsum[idx] = 0.0f;
}

__global__ void finalize_out(float* __restrict__ out, const float* __restrict__ fc_b) {
    int idx = blockIdx.x * blockDim.x + threadIdx.x;
    if (idx < BATCH * TT) out[idx] = g_predsum[idx] + fc_b[0];
}

// ---------------------------------------------------------------------------
// Step kernel: GEMM (tile 128x64, K=1024) + fused LSTM cell epilogue
// 256 threads = 8 warps; warp tile 64x16: warp_m = wid&1, warp_n = wid>>1.
// 3 CTAs/SM (launch_bounds) -> 24 warps/SM hide barrier/ldsm stalls.
// ---------------------------------------------------------------------------
__global__ void __launch_bounds__(NTHREADS, 3)
step_kernel(int t, const float* __restrict__ future_fd, const float* __restrict__ fc_b) {
    const __half* __restrict__ Asrc = g_Aext[t & 1];
    __half* __restrict__ Adst = g_Aext[(t + 1) & 1];

    extern __shared__ char smem_raw[];
    uint32_t sb = smem_u32(smem_raw);
    uint32_t ab = (sb + 1023u) & ~1023u;
    char* smem = smem_raw + (ab - sb);
    const uint32_t tiles = ab;

    const int tid = threadIdx.x;
    const int wid = tid >> 5;
    const int lid = tid & 31;
    const int wm = wid & 1;          // 0..1  (64-row block)
    const int wn = wid >> 1;         // 0..3  (16-col block)
    const int m0 = blockIdx.x * TM;
    const int n0 = blockIdx.y * TN;

    // ---- chunk loader: 192 rows x 128B (A rows 0..127, B rows 0..63) -------
    auto load_chunk = [&](int c, int s) {
        const int k0 = c * KC;
        const uint32_t base = tiles + s * STAGE_BYTES;
        #pragma unroll
        for (int j = 0; j < 6; j++) {
            int li = tid + j * NTHREADS;      // 0..1535
            int ri = li >> 3, q = li & 7;
            if (ri < TM) {
                uint32_t dst = base + sw128((uint32_t)(ri * 128 + q * 16));
                cp_async16(dst, Asrc + ((size_t)(m0 + ri) * KE + k0 + q * 8));
            } else {
                int rb = ri - TM;             // 0..63
                uint32_t dst = base + 16384 + sw128((uint32_t)(rb * 128 + q * 16));
                cp_async16(dst, g_Wext + ((size_t)(n0 + rb) * KE + k0 + q * 8));
            }
        }
        cp_commit();
    };

    // ---- lane constants for ldmatrix addressing ----------------------------
    const int a_lr = lid & 15;                      // A row within 16
    const int a_ch = (lid >> 4) << 4;               // A k-byte offset (0/16)
    const int b_nr = (lid & 7) + ((lid >> 4) << 3); // B n-row within 16
    const int b_ch = ((lid >> 3) & 1) << 4;         // B k-byte offset (0/16)

    float acc[4][2][4];
    #pragma unroll
    for (int i = 0; i < 4; i++)
        #pragma unroll
        for (int j = 0; j < 2; j++)
            #pragma unroll
            for (int r = 0; r < 4; r++) acc[i][j][r] = 0.0f;

    load_chunk(0, 0);
    load_chunk(1, 1);

    #pragma unroll 1
    for (int c = 0; c < NCH; c++) {
        if (c < NCH - 2) asm volatile("cp.async.wait_group 1;" ::: "memory");
        else             asm volatile("cp.async.wait_group 0;" ::: "memory");
        __syncthreads();

        if (c + 2 < NCH) load_chunk(c + 2, (c + 2) % STAGES);

        const uint32_t As = tiles + (c % STAGES) * STAGE_BYTES;
        const uint32_t Bs = As + 16384;

        #pragma unroll
        for (int ks = 0; ks < 4; ks++) {
            uint32_t a[4][4], b[2][2];
            #pragma unroll
            for (int mi = 0; mi < 4; mi++) {
                uint32_t off = (uint32_t)((wm * 64 + mi * 16 + a_lr) * 128 + ks * 32 + a_ch);
                ldsm_x4(a[mi][0], a[mi][1], a[mi][2], a[mi][3], As + sw128(off));
            }
            {
                uint32_t off = (uint32_t)((wn * 16 + b_nr) * 128 + ks * 32 + b_ch);
                ldsm_x4(b[0][0], b[0][1], b[1][0], b[1][1], Bs + sw128(off));
            }
            #pragma unroll
            for (int mi = 0; mi < 4; mi++)
                #pragma unroll
                for (int j = 0; j < 2; j++)
                    mma_fp16(acc[mi][j], a[mi], b[j]);
        }
    }
    __syncthreads();   // smem stages now reusable as epilogue scratch

    // ---- epilogue: gates -> smem, fused cell update ------------------------
    float* gates = (float*)smem;                  // 128 rows x GPITCH floats
    const int g = lid >> 2, tg = lid & 3;
    const float fcb = fc_b[0];

    {
        const int clb = wn * 16;
        #pragma unroll
        for (int mi = 0; mi < 4; mi++) {
            const int r = wm * 64 + mi * 16 + g;
            #pragma unroll
            for (int j = 0; j < 2; j++) {
                const int cl = clb + j * 8 + 2 * tg;
                *(float2*)&gates[r * GPITCH + cl] =
                    make_float2(acc[mi][j][0], acc[mi][j][1]);
                *(float2*)&gates[(r + 8) * GPITCH + cl] =
                    make_float2(acc[mi][j][2], acc[mi][j][3]);
            }
        }
    }
    __syncthreads();

    #pragma unroll 2
    for (int jj = 0; jj < 8; jj++) {
        const int idx = tid + jj * NTHREADS;       // 2048 = 128 rows x 16 units
        const int row = idx >> 4, u = idx & 15;
        const int n = n0 + 4 * u;
        const int ug = n >> 2;                     // global unit 0..1023
        const int b = m0 + row;

        float4 gv = *(float4*)&gates[row * GPITCH + 4 * u];
        float4 bs = ((const float4*)g_bias)[ug];
        float4 w0 = ((const float4*)g_w0)[ug];
        float4 w1 = ((const float4*)g_w1)[ug];

        float prev = 0.0f;
        if (t > 0) prev = g_predsum[b * TT + (t - 1)] + fcb;
        const float fdv = future_fd[b * TT + t];

        float gi = gv.x + bs.x + prev * w0.x + fdv * w1.x;
        float gf = gv.y + bs.y + prev * w0.y + fdv * w1.y;
        float gg = gv.z + bs.z + prev * w0.z + fdv * w1.z;
        float go = gv.w + bs.w + prev * w0.w + fdv * w1.w;

        float co = g_c[(size_t)b * HH + ug];
        float cn = sigf(gf) * co + sigf(gi) * tanh_f(gg);
        float h  = sigf(go) * tanh_f(cn);
        g_c[(size_t)b * HH + ug] = cn;
        Adst[(size_t)b * KE + ug] = __float2half(h);

        float fcp = h * g_fcW[ug];
        fcp += __shfl_xor_sync(0xFFFFFFFFu, fcp, 1);
        fcp += __shfl_xor_sync(0xFFFFFFFFu, fcp, 2);
        fcp += __shfl_xor_sync(0xFFFFFFFFu, fcp, 4);
        fcp += __shfl_xor_sync(0xFFFFFFFFu, fcp, 8);
        if ((lid & 15) == 0) atomicAdd(&g_predsum[b * TT + t], fcp);
    }
}

// ---------------------------------------------------------------------------
// Host launcher
// ---------------------------------------------------------------------------
extern "C" void kernel_launch(void* const* d_in, const int* in_sizes, int n_in,
                              void* d_out, int out_size) {
    const float* future_fd = (const float*)d_in[0];
    const float* hidden    = (const float*)d_in[1];
    const float* cell      = (const float*)d_in[2];
    const float* W_ih      = (const float*)d_in[3];
    const float* W_hh      = (const float*)d_in[4];
    const float* b_ih      = (const float*)d_in[5];
    const float* b_hh      = (const float*)d_in[6];
    const float* fc_W      = (const float*)d_in[7];
    const float* fc_b      = (const float*)d_in[8];

    cudaFuncSetAttribute(step_kernel, cudaFuncAttributeMaxDynamicSharedMemorySize, SMEM_BYTES);

    prep_weights<<<(N4 * HH) / 256, 256>>>(W_hh, W_ih, b_ih, b_hh, fc_W);
    prep_state<<<(BATCH * HH) / 256, 256>>>(hidden, cell);
    for (int t = 0; t < TT; t++) {
        step_kernel<<<dim3(BATCH / TM, N4 / TN), NTHREADS, SMEM_BYTES>>>(t, future_fd, fc_b);
    }
    finalize_out<<<(BATCH * TT + 255) / 256, 256>>>((float*)d_out, fc_b);
}